// round 13
// baseline (speedup 1.0000x reference)
#include <cuda_runtime.h>
#include <cuda_bf16.h>
#include <cstdint>

#define S_LEN 8192
#define HID   2048
#define DIN   2048

#define NCTA  128          // scan CTAs
#define ROWS_PER_CTA 16    // 2048 / 128
#define TPB   512
#define GEMM_CTAS 20       // persistent GEMM CTAs (SMs 128..147)
#define N_WORKERS (GEMM_CTAS * 2)   // two 256-thread halves per GEMM CTA

#define BM 128
#define BN 128
#define BK 16
#define N_TILES ((S_LEN / BM) * (HID / BN))   // 64 x 16 = 1024, m-major

#define SENT 0x7fbfffffu   // NaN bit pattern: tanh/xp can never equal this

// ---------------- device scratch (no allocation allowed) ----------------
__device__ float g_xp[(size_t)S_LEN * HID];   // 64 MB input projection (sentinel-poisoned)
__device__ float g_hr[4][HID];                // 4-deep hidden-state ring

// packed fp32x2 FMA (sm_100+ FFMA2 path — only reachable via PTX)
__device__ __forceinline__ unsigned long long fma_f32x2(
    unsigned long long a, unsigned long long b, unsigned long long c) {
    unsigned long long d;
    asm("fma.rn.f32x2 %0, %1, %2, %3;" : "=l"(d) : "l"(a), "l"(b), "l"(c));
    return d;
}
__device__ __forceinline__ unsigned long long pack_f32x2(float lo, float hi) {
    unsigned long long d;
    asm("mov.b64 %0, {%1, %2};" : "=l"(d) : "f"(lo), "f"(hi));
    return d;
}
__device__ __forceinline__ void unpack_f32x2(unsigned long long v, float& lo, float& hi) {
    asm("mov.b64 {%0, %1}, %2;" : "=f"(lo), "=f"(hi) : "l"(v));
}
__device__ __forceinline__ uint4 ld_vol4(const uint4* p) {
    uint4 v;
    asm volatile("ld.volatile.global.v4.u32 {%0,%1,%2,%3}, [%4];"
                 : "=r"(v.x), "=r"(v.y), "=r"(v.z), "=r"(v.w) : "l"(p) : "memory");
    return v;
}
__device__ __forceinline__ unsigned ld_vol_u32(const unsigned* p) {
    unsigned v;
    asm volatile("ld.volatile.global.u32 %0, [%1];" : "=r"(v) : "l"(p) : "memory");
    return v;
}
__device__ __forceinline__ void st_vol_f32(float* p, float v) {
    asm volatile("st.volatile.global.f32 [%0], %1;" :: "l"(p), "f"(v) : "memory");
}
__device__ __forceinline__ void st_vol_u32(unsigned* p, unsigned v) {
    asm volatile("st.volatile.global.u32 [%0], %1;" :: "l"(p), "r"(v) : "memory");
}

// ---------------- init: poison xp + reset h ring (every launch) ----------------
__global__ void poison_kernel() {
    const size_t stride = (size_t)gridDim.x * blockDim.x;
    size_t i = (size_t)blockIdx.x * blockDim.x + threadIdx.x;
    uint4* xp4 = (uint4*)g_xp;
    const size_t n4 = (size_t)S_LEN * HID / 4;
    uint4 s4 = make_uint4(SENT, SENT, SENT, SENT);
    for (size_t k = i; k < n4; k += stride) xp4[k] = s4;
    if (i < 4 * HID) ((unsigned*)g_hr)[i] = (i < HID) ? 0u : SENT;
}

// ---------------- fused kernel: 128 scan CTAs + 20 GEMM CTAs, one wave ----------------
// SMEM is shared (union) between the two paths.
#define SMEM_BYTES 33792   // max(GEMM: 2*(16*132)*4*2 = 33792, SCAN: 8192+1280)

__global__ __launch_bounds__(TPB, 1) void fused_kernel(
    const float* __restrict__ X,
    const float* __restrict__ Wi,
    const float* __restrict__ bi,
    const float* __restrict__ Wh,
    const float* __restrict__ bh,
    float* __restrict__ out,
    int write_tail)
{
    __shared__ __align__(16) char smem_raw[SMEM_BYTES];

    const int bid = blockIdx.x;
    const int tid = threadIdx.x;

    typedef unsigned long long ull;
    union Pk { float4 f; uint4 i; ull u[2]; };

    if (bid < NCTA) {
        // ================= SCAN PATH (R12 structure + fused xp poll) =================
        uint4* sh_h = (uint4*)smem_raw;                        // 8 KB
        float (*red)[20] = (float(*)[20])(smem_raw + 8192);    // 16 x 20 floats

        const int w     = tid >> 5;
        const int lane  = tid & 31;
        const int kg_lo = lane & 7;
        const int rg    = lane >> 3;
        const int kg    = w * 8 + kg_lo;
        const int row0  = bid * ROWS_PER_CTA + rg * 4;

        // preload Wh, packed as f32x2
        ull Wp[4][8];
#pragma unroll
        for (int r = 0; r < 4; r++)
#pragma unroll
            for (int i = 0; i < 4; i++) {
                Pk v;
                v.f = *(const float4*)&Wh[(size_t)(row0 + r) * HID + kg * 4 + i * 512];
                Wp[r][2 * i]     = v.u[0];
                Wp[r][2 * i + 1] = v.u[1];
            }

        // warp-0 tail state: lane pair (2L, 2L+1) handles row L
        const int trow = lane >> 1;
        const float bhv = bh[bid * ROWS_PER_CTA + trow];
        const unsigned* xp_col = (const unsigned*)&g_xp[bid * ROWS_PER_CTA + trow];

        for (int t = 0; t < S_LEN; t++) {
            // Phase A: fused spin — h chunk (all warps) + xp value (warp 0 only).
            unsigned xb = 0u;
            {
                const uint4* hp4 = (const uint4*)g_hr[t & 3] + tid;
                const unsigned* xpp = xp_col + (size_t)t * HID;
                uint4 hv = ld_vol4(hp4);
                bool xok = (w != 0);
                if (!xok) { xb = ld_vol_u32(xpp); xok = (xb != SENT); }
                bool hok = !(hv.x == SENT || hv.y == SENT ||
                             hv.z == SENT || hv.w == SENT);
                while (!(hok && xok)) {
                    if (!hok) {
                        hv = ld_vol4(hp4);
                        hok = !(hv.x == SENT || hv.y == SENT ||
                                hv.z == SENT || hv.w == SENT);
                    }
                    if (!xok) { xb = ld_vol_u32(xpp); xok = (xb != SENT); }
                }
                sh_h[tid] = hv;
            }
            __syncthreads();

            // sentinel-reset own rows of the dead slot (h_{t-1}'s slot); safe:
            // gather of h_t complete => all CTAs finished reading h_{t-1}
            if (w == 1 && lane < ROWS_PER_CTA) {
                st_vol_u32((unsigned*)&g_hr[(t + 3) & 3][bid * ROWS_PER_CTA + lane], SENT);
            }

            // Phase B: packed FMA from SMEM h
            Pk h0, h1, h2, h3;
            h0.i = sh_h[kg +   0];
            h1.i = sh_h[kg + 128];
            h2.i = sh_h[kg + 256];
            h3.i = sh_h[kg + 384];
            ull hp[8] = { h0.u[0], h0.u[1], h1.u[0], h1.u[1],
                          h2.u[0], h2.u[1], h3.u[0], h3.u[1] };

            ull a2[4] = {0ull, 0ull, 0ull, 0ull};
#pragma unroll
            for (int r = 0; r < 4; r++)
#pragma unroll
                for (int i = 0; i < 8; i++)
                    a2[r] = fma_f32x2(Wp[r][i], hp[i], a2[r]);

            float acc[4];
#pragma unroll
            for (int r = 0; r < 4; r++) {
                float lo, hi;
                unpack_f32x2(a2[r], lo, hi);
                acc[r] = lo + hi;
            }

            // reduce across the 8 kg_lo lanes within each rg group
#pragma unroll
            for (int d = 1; d < 8; d <<= 1) {
                acc[0] += __shfl_xor_sync(0xffffffffu, acc[0], d);
                acc[1] += __shfl_xor_sync(0xffffffffu, acc[1], d);
                acc[2] += __shfl_xor_sync(0xffffffffu, acc[2], d);
                acc[3] += __shfl_xor_sync(0xffffffffu, acc[3], d);
            }
            if (kg_lo == 0) {
                red[rg * 4 + 0][w] = acc[0];
                red[rg * 4 + 1][w] = acc[1];
                red[rg * 4 + 2][w] = acc[2];
                red[rg * 4 + 3][w] = acc[3];
            }

            if (w == 0) {
                asm volatile("bar.sync 1, %0;" :: "r"(TPB) : "memory");
                // tail: lane pair (2L, 2L+1) -> row L
                const int half = lane & 1;
                float4 p0 = *(const float4*)&red[trow][half * 8];
                float4 p1 = *(const float4*)&red[trow][half * 8 + 4];
                float s = ((p0.x + p0.y) + (p0.z + p0.w))
                        + ((p1.x + p1.y) + (p1.z + p1.w));
                s += __shfl_xor_sync(0xffffffffu, s, 1);   // both lanes: full row sum
                float v = tanhf(s + bhv + __uint_as_float(xb));
                int j = bid * ROWS_PER_CTA + trow;
                if (half == 0) {
                    // RELEASE: even lanes -> 16x4B consecutive, one 64B txn
                    st_vol_f32(&g_hr[(t + 1) & 3][j], v);
                } else {
                    // off the release path: odd lanes store out[t] (+ h_n)
                    __stcs(&out[(size_t)t * HID + j], v);
                    if (write_tail && t == S_LEN - 1)
                        out[(size_t)S_LEN * HID + j] = v;
                }
            } else {
                asm volatile("bar.arrive 1, %0;" :: "r"(TPB) : "memory");
            }
            // no grid barrier: next iteration's spin-gather provides the wait
        }
    } else {
        // ================= GEMM WORKER PATH (xp producer) =================
        // Two independent 256-thread halves per CTA; each runs 128x128x16-tile
        // GEMM over tiles assigned round-robin in m-major order.
        const int half  = tid >> 8;          // 0 or 1
        const int htid  = tid & 255;
        const int worker = (bid - NCTA) * 2 + half;   // 0..39
        const int bar_id = 2 + half;

        float (*As)[BM + 4] = (float(*)[BM + 4])(smem_raw + half * 8448);
        float (*Bs)[BM + 4] = (float(*)[BM + 4])(smem_raw + 16896 + half * 8448);

        const int tx = htid & 15;
        const int ty = htid >> 4;
        const int lrow = htid >> 2;
        const int lk   = (htid & 3) * 4;

        union F4U { float4 f; ull u[2]; };

        for (int tile = worker; tile < N_TILES; tile += N_WORKERS) {
            const int m0 = (tile >> 4) * BM;   // m-major: rows produced in order
            const int n0 = (tile & 15) * BN;

            const float* Ag = X  + (size_t)m0 * DIN;
            const float* Bg = Wi + (size_t)n0 * DIN;

            ull acc2[4][8];
#pragma unroll
            for (int ip = 0; ip < 4; ip++)
#pragma unroll
                for (int j = 0; j < 8; j++) acc2[ip][j] = 0ull;

            for (int kk = 0; kk < DIN; kk += BK) {
#pragma unroll
                for (int q = 0; q < 2; q++) {
                    int r = lrow + 64 * q;
                    float4 va = *(const float4*)&Ag[(size_t)r * DIN + kk + lk];
                    As[lk + 0][r] = va.x; As[lk + 1][r] = va.y;
                    As[lk + 2][r] = va.z; As[lk + 3][r] = va.w;
                    float4 vb = *(const float4*)&Bg[(size_t)r * DIN + kk + lk];
                    Bs[lk + 0][r] = vb.x; Bs[lk + 1][r] = vb.y;
                    Bs[lk + 2][r] = vb.z; Bs[lk + 3][r] = vb.w;
                }
                asm volatile("bar.sync %0, 256;" :: "r"(bar_id) : "memory");

#pragma unroll
                for (int k = 0; k < BK; k++) {
                    F4U a0, a1;
                    a0.f = *(const float4*)&As[k][ty * 8];
                    a1.f = *(const float4*)&As[k][ty * 8 + 4];
                    ull ap[4] = { a0.u[0], a0.u[1], a1.u[0], a1.u[1] };
                    float b[8];
                    *(float4*)&b[0] = *(const float4*)&Bs[k][tx * 8];
                    *(float4*)&b[4] = *(const float4*)&Bs[k][tx * 8 + 4];
#pragma unroll
                    for (int j = 0; j < 8; j++) {
                        ull bb = pack_f32x2(b[j], b[j]);
#pragma unroll
                        for (int ip = 0; ip < 4; ip++)
                            acc2[ip][j] = fma_f32x2(ap[ip], bb, acc2[ip][j]);
                    }
                }
                asm volatile("bar.sync %0, 256;" :: "r"(bar_id) : "memory");
            }

            // epilogue: unpack, add bias, store (visible to scan pollers via L2)
#pragma unroll
            for (int ip = 0; ip < 4; ip++) {
                float row0v[8], row1v[8];
#pragma unroll
                for (int j = 0; j < 8; j++) unpack_f32x2(acc2[ip][j], row0v[j], row1v[j]);
                int m_a = m0 + ty * 8 + 2 * ip;
                int m_b = m_a + 1;
#pragma unroll
                for (int j = 0; j < 8; j += 4) {
                    int n = n0 + tx * 8 + j;
                    float4 v;
                    v.x = row0v[j + 0] + bi[n + 0];
                    v.y = row0v[j + 1] + bi[n + 1];
                    v.z = row0v[j + 2] + bi[n + 2];
                    v.w = row0v[j + 3] + bi[n + 3];
                    *(float4*)&g_xp[(size_t)m_a * HID + n] = v;
                    float4 u;
                    u.x = row1v[j + 0] + bi[n + 0];
                    u.y = row1v[j + 1] + bi[n + 1];
                    u.z = row1v[j + 2] + bi[n + 2];
                    u.w = row1v[j + 3] + bi[n + 3];
                    *(float4*)&g_xp[(size_t)m_b * HID + n] = u;
                }
            }
        }
    }
}

// ---------------- launch ----------------
extern "C" void kernel_launch(void* const* d_in, const int* in_sizes, int n_in,
                              void* d_out, int out_size) {
    const float* x  = (const float*)d_in[0];
    const float* Wi = (const float*)d_in[1];
    const float* bi = (const float*)d_in[2];
    const float* Wh = (const float*)d_in[3];
    const float* bh = (const float*)d_in[4];
    float* out = (float*)d_out;

    poison_kernel<<<2048, 256>>>();

    int write_tail = (out_size >= S_LEN * HID + HID) ? 1 : 0;
    fused_kernel<<<NCTA + GEMM_CTAS, TPB>>>(x, Wi, bi, Wh, bh, out, write_tail);
}

// round 15
// speedup vs baseline: 1.1543x; 1.1543x over previous
#include <cuda_runtime.h>
#include <cuda_bf16.h>
#include <cstdint>

#define S_LEN 8192
#define HID   2048
#define DIN   2048

#define NCTA  128          // scan CTAs
#define ROWS_PER_CTA 16    // 2048 / 128
#define TPB   512
#define GEMM_CTAS 20       // persistent GEMM CTAs
#define N_WORKERS (GEMM_CTAS * 2)   // two 256-thread halves per GEMM CTA

#define BM 128
#define BN 128
#define BK 16
#define NKB (DIN / BK)                        // 128 k-blocks per tile
#define N_TILES ((S_LEN / BM) * (HID / BN))   // 1024, m-major

#define SENT 0x7fbfffffu   // NaN bit pattern: tanh/xp can never equal this

// GEMM SMEM: per half, double-buffered k-major As/Bs (16 x 132 floats each)
#define AB_BYTES   8448                 // 16*132*4
#define BUF_BYTES  (2 * AB_BYTES)       // A + B one stage
#define HALF_BYTES (2 * BUF_BYTES)      // double buffer
#define SMEM_DYN   (2 * HALF_BYTES)     // 67584; scan uses first 9472 bytes

// ---------------- device scratch (no allocation allowed) ----------------
__device__ float g_xp[(size_t)S_LEN * HID];   // 64 MB input projection (sentinel-poisoned)
__device__ float g_hr[4][HID];                // 4-deep hidden-state ring

// packed fp32x2 FMA (sm_100+ FFMA2 path — only reachable via PTX)
__device__ __forceinline__ unsigned long long fma_f32x2(
    unsigned long long a, unsigned long long b, unsigned long long c) {
    unsigned long long d;
    asm("fma.rn.f32x2 %0, %1, %2, %3;" : "=l"(d) : "l"(a), "l"(b), "l"(c));
    return d;
}
__device__ __forceinline__ unsigned long long pack_f32x2(float lo, float hi) {
    unsigned long long d;
    asm("mov.b64 %0, {%1, %2};" : "=l"(d) : "f"(lo), "f"(hi));
    return d;
}
__device__ __forceinline__ void unpack_f32x2(unsigned long long v, float& lo, float& hi) {
    asm("mov.b64 {%0, %1}, %2;" : "=f"(lo), "=f"(hi) : "l"(v));
}
__device__ __forceinline__ uint4 ld_vol4(const uint4* p) {
    uint4 v;
    asm volatile("ld.volatile.global.v4.u32 {%0,%1,%2,%3}, [%4];"
                 : "=r"(v.x), "=r"(v.y), "=r"(v.z), "=r"(v.w) : "l"(p) : "memory");
    return v;
}
__device__ __forceinline__ unsigned ld_vol_u32(const unsigned* p) {
    unsigned v;
    asm volatile("ld.volatile.global.u32 %0, [%1];" : "=r"(v) : "l"(p) : "memory");
    return v;
}
__device__ __forceinline__ void st_vol_f32(float* p, float v) {
    asm volatile("st.volatile.global.f32 [%0], %1;" :: "l"(p), "f"(v) : "memory");
}
__device__ __forceinline__ void st_vol_u32(unsigned* p, unsigned v) {
    asm volatile("st.volatile.global.u32 [%0], %1;" :: "l"(p), "r"(v) : "memory");
}
__device__ __forceinline__ void cp_async4(uint32_t smem_addr, const void* gptr) {
    asm volatile("cp.async.ca.shared.global [%0], [%1], 4;"
                 :: "r"(smem_addr), "l"(gptr));
}
__device__ __forceinline__ void cp_async_commit() {
    asm volatile("cp.async.commit_group;" ::: "memory");
}
__device__ __forceinline__ void cp_async_wait_all() {
    asm volatile("cp.async.wait_group 0;" ::: "memory");
}

// ---------------- init: poison xp + reset h ring (every launch) ----------------
__global__ void poison_kernel() {
    const size_t stride = (size_t)gridDim.x * blockDim.x;
    size_t i = (size_t)blockIdx.x * blockDim.x + threadIdx.x;
    uint4* xp4 = (uint4*)g_xp;
    const size_t n4 = (size_t)S_LEN * HID / 4;
    uint4 s4 = make_uint4(SENT, SENT, SENT, SENT);
    for (size_t k = i; k < n4; k += stride) xp4[k] = s4;
    if (i < 4 * HID) ((unsigned*)g_hr)[i] = (i < HID) ? 0u : SENT;
}

// ---------------- fused kernel: 128 scan CTAs + 20 GEMM CTAs, one wave ----------------
__global__ __launch_bounds__(TPB, 1) void fused_kernel(
    const float* __restrict__ X,
    const float* __restrict__ Wi,
    const float* __restrict__ bi,
    const float* __restrict__ Wh,
    const float* __restrict__ bh,
    float* __restrict__ out,
    int write_tail)
{
    extern __shared__ __align__(16) char dsmem[];

    const int bid = blockIdx.x;
    const int tid = threadIdx.x;

    typedef unsigned long long ull;
    union Pk { float4 f; uint4 i; ull u[2]; };

    if (bid < NCTA) {
        // ================= SCAN PATH (R12/R13 proven structure) =================
        uint4* sh_h = (uint4*)dsmem;                        // 8 KB
        float (*red)[20] = (float(*)[20])(dsmem + 8192);    // 16 x 20 floats

        const int w     = tid >> 5;
        const int lane  = tid & 31;
        const int kg_lo = lane & 7;
        const int rg    = lane >> 3;
        const int kg    = w * 8 + kg_lo;
        const int row0  = bid * ROWS_PER_CTA + rg * 4;

        // preload Wh, packed as f32x2
        ull Wp[4][8];
#pragma unroll
        for (int r = 0; r < 4; r++)
#pragma unroll
            for (int i = 0; i < 4; i++) {
                Pk v;
                v.f = *(const float4*)&Wh[(size_t)(row0 + r) * HID + kg * 4 + i * 512];
                Wp[r][2 * i]     = v.u[0];
                Wp[r][2 * i + 1] = v.u[1];
            }

        // warp-0 tail state: lane pair (2L, 2L+1) handles row L
        const int trow = lane >> 1;
        const float bhv = bh[bid * ROWS_PER_CTA + trow];
        const unsigned* xp_col = (const unsigned*)&g_xp[bid * ROWS_PER_CTA + trow];

        for (int t = 0; t < S_LEN; t++) {
            // Phase A: fused spin — h chunk (all warps) + xp value (warp 0 only).
            unsigned xb = 0u;
            {
                const uint4* hp4 = (const uint4*)g_hr[t & 3] + tid;
                const unsigned* xpp = xp_col + (size_t)t * HID;
                uint4 hv = ld_vol4(hp4);
                bool xok = (w != 0);
                if (!xok) { xb = ld_vol_u32(xpp); xok = (xb != SENT); }
                bool hok = !(hv.x == SENT || hv.y == SENT ||
                             hv.z == SENT || hv.w == SENT);
                while (!(hok && xok)) {
                    if (!hok) {
                        hv = ld_vol4(hp4);
                        hok = !(hv.x == SENT || hv.y == SENT ||
                                hv.z == SENT || hv.w == SENT);
                    }
                    if (!xok) { xb = ld_vol_u32(xpp); xok = (xb != SENT); }
                }
                sh_h[tid] = hv;
            }
            __syncthreads();

            // sentinel-reset own rows of the dead slot (h_{t-1}'s slot)
            if (w == 1 && lane < ROWS_PER_CTA) {
                st_vol_u32((unsigned*)&g_hr[(t + 3) & 3][bid * ROWS_PER_CTA + lane], SENT);
            }

            // Phase B: packed FMA from SMEM h
            Pk h0, h1, h2, h3;
            h0.i = sh_h[kg +   0];
            h1.i = sh_h[kg + 128];
            h2.i = sh_h[kg + 256];
            h3.i = sh_h[kg + 384];
            ull hp[8] = { h0.u[0], h0.u[1], h1.u[0], h1.u[1],
                          h2.u[0], h2.u[1], h3.u[0], h3.u[1] };

            ull a2[4] = {0ull, 0ull, 0ull, 0ull};
#pragma unroll
            for (int r = 0; r < 4; r++)
#pragma unroll
                for (int i = 0; i < 8; i++)
                    a2[r] = fma_f32x2(Wp[r][i], hp[i], a2[r]);

            float acc[4];
#pragma unroll
            for (int r = 0; r < 4; r++) {
                float lo, hi;
                unpack_f32x2(a2[r], lo, hi);
                acc[r] = lo + hi;
            }

            // reduce across the 8 kg_lo lanes within each rg group
#pragma unroll
            for (int d = 1; d < 8; d <<= 1) {
                acc[0] += __shfl_xor_sync(0xffffffffu, acc[0], d);
                acc[1] += __shfl_xor_sync(0xffffffffu, acc[1], d);
                acc[2] += __shfl_xor_sync(0xffffffffu, acc[2], d);
                acc[3] += __shfl_xor_sync(0xffffffffu, acc[3], d);
            }
            if (kg_lo == 0) {
                red[rg * 4 + 0][w] = acc[0];
                red[rg * 4 + 1][w] = acc[1];
                red[rg * 4 + 2][w] = acc[2];
                red[rg * 4 + 3][w] = acc[3];
            }

            if (w == 0) {
                asm volatile("bar.sync 1, %0;" :: "r"(TPB) : "memory");
                // tail: lane pair (2L, 2L+1) -> row L
                const int half = lane & 1;
                float4 p0 = *(const float4*)&red[trow][half * 8];
                float4 p1 = *(const float4*)&red[trow][half * 8 + 4];
                float s = ((p0.x + p0.y) + (p0.z + p0.w))
                        + ((p1.x + p1.y) + (p1.z + p1.w));
                s += __shfl_xor_sync(0xffffffffu, s, 1);   // both lanes: full row sum
                float v = tanhf(s + bhv + __uint_as_float(xb));
                int j = bid * ROWS_PER_CTA + trow;
                if (half == 0) {
                    // RELEASE: even lanes -> 16x4B consecutive, one 64B txn
                    st_vol_f32(&g_hr[(t + 1) & 3][j], v);
                } else {
                    // off the release path: odd lanes store out[t] (+ h_n)
                    __stcs(&out[(size_t)t * HID + j], v);
                    if (write_tail && t == S_LEN - 1)
                        out[(size_t)S_LEN * HID + j] = v;
                }
            } else {
                asm volatile("bar.arrive 1, %0;" :: "r"(TPB) : "memory");
            }
            // no grid barrier: next iteration's spin-gather provides the wait
        }
    } else {
        // ================= GEMM WORKER PATH (xp producer) =================
        // Two independent 256-thread halves; cp.async double-buffered pipeline:
        //   wait_group 0; bar; issue k-block kb+1; compute kb.
        // GMEM latency hides under the ~1000-cyc compute of the current block.
        const int half  = tid >> 8;          // 0 or 1
        const int htid  = tid & 255;
        const int worker = (bid - NCTA) * 2 + half;   // 0..39
        const int bar_id = 2 + half;

        char* hbase = dsmem + half * HALF_BYTES;
        const uint32_t hbase_s = (uint32_t)__cvta_generic_to_shared(hbase);

        const int tx = htid & 15;
        const int ty = htid >> 4;
        // staging map: element v (0..7): g = htid + 256*v; k = g&15; r = g>>4
        // global: row r, col kk+k (coalesced 4B); smem: As[k][r] (k-major, stride 132)

        union F4U { float4 f; ull u[2]; };

        for (int tile = worker; tile < N_TILES; tile += N_WORKERS) {
            const int m0 = (tile >> 4) * BM;   // m-major: timesteps produced in order
            const int n0 = (tile & 15) * BN;

            const float* Ag = X  + (size_t)m0 * DIN;
            const float* Bg = Wi + (size_t)n0 * DIN;

            ull acc2[4][8];
#pragma unroll
            for (int ip = 0; ip < 4; ip++)
#pragma unroll
                for (int j = 0; j < 8; j++) acc2[ip][j] = 0ull;

            // prologue: stage k-block 0 into buffer 0
            {
                const int kk = 0;
#pragma unroll
                for (int v = 0; v < 8; v++) {
                    int g = htid + 256 * v;
                    int k = g & 15, r = g >> 4;
                    uint32_t soff = (uint32_t)((k * 132 + r) * 4);
                    cp_async4(hbase_s + soff, Ag + (size_t)r * DIN + kk + k);
                    cp_async4(hbase_s + AB_BYTES + soff, Bg + (size_t)r * DIN + kk + k);
                }
                cp_async_commit();
            }

            for (int kb = 0; kb < NKB; kb++) {
                cp_async_wait_all();
                asm volatile("bar.sync %0, 256;" :: "r"(bar_id) : "memory");

                if (kb + 1 < NKB) {   // issue next block into the other buffer
                    const int kk = (kb + 1) * BK;
                    const uint32_t nb = hbase_s + ((kb + 1) & 1) * BUF_BYTES;
#pragma unroll
                    for (int v = 0; v < 8; v++) {
                        int g = htid + 256 * v;
                        int k = g & 15, r = g >> 4;
                        uint32_t soff = (uint32_t)((k * 132 + r) * 4);
                        cp_async4(nb + soff, Ag + (size_t)r * DIN + kk + k);
                        cp_async4(nb + AB_BYTES + soff, Bg + (size_t)r * DIN + kk + k);
                    }
                    cp_async_commit();
                }

                // compute on current buffer
                const float* As = (const float*)(hbase + (kb & 1) * BUF_BYTES);
                const float* Bs = As + AB_BYTES / 4;
#pragma unroll
                for (int k = 0; k < BK; k++) {
                    F4U a0, a1;   // a-pairs come free from the vector load
                    a0.f = *(const float4*)&As[k * 132 + ty * 8];
                    a1.f = *(const float4*)&As[k * 132 + ty * 8 + 4];
                    ull ap[4] = { a0.u[0], a0.u[1], a1.u[0], a1.u[1] };
                    float b[8];
                    *(float4*)&b[0] = *(const float4*)&Bs[k * 132 + tx * 8];
                    *(float4*)&b[4] = *(const float4*)&Bs[k * 132 + tx * 8 + 4];
#pragma unroll
                    for (int j = 0; j < 8; j++) {
                        ull bb = pack_f32x2(b[j], b[j]);
#pragma unroll
                        for (int ip = 0; ip < 4; ip++)
                            acc2[ip][j] = fma_f32x2(ap[ip], bb, acc2[ip][j]);
                    }
                }
            }
            asm volatile("bar.sync %0, 256;" :: "r"(bar_id) : "memory");

            // epilogue: unpack, add bias, store (visible to scan pollers via L2)
#pragma unroll
            for (int ip = 0; ip < 4; ip++) {
                float row0v[8], row1v[8];
#pragma unroll
                for (int j = 0; j < 8; j++) unpack_f32x2(acc2[ip][j], row0v[j], row1v[j]);
                int m_a = m0 + ty * 8 + 2 * ip;
                int m_b = m_a + 1;
#pragma unroll
                for (int j = 0; j < 8; j += 4) {
                    int n = n0 + tx * 8 + j;
                    float4 v;
                    v.x = row0v[j + 0] + bi[n + 0];
                    v.y = row0v[j + 1] + bi[n + 1];
                    v.z = row0v[j + 2] + bi[n + 2];
                    v.w = row0v[j + 3] + bi[n + 3];
                    *(float4*)&g_xp[(size_t)m_a * HID + n] = v;
                    float4 u;
                    u.x = row1v[j + 0] + bi[n + 0];
                    u.y = row1v[j + 1] + bi[n + 1];
                    u.z = row1v[j + 2] + bi[n + 2];
                    u.w = row1v[j + 3] + bi[n + 3];
                    *(float4*)&g_xp[(size_t)m_b * HID + n] = u;
                }
            }
        }
    }
}

// ---------------- launch ----------------
extern "C" void kernel_launch(void* const* d_in, const int* in_sizes, int n_in,
                              void* d_out, int out_size) {
    const float* x  = (const float*)d_in[0];
    const float* Wi = (const float*)d_in[1];
    const float* bi = (const float*)d_in[2];
    const float* Wh = (const float*)d_in[3];
    const float* bh = (const float*)d_in[4];
    float* out = (float*)d_out;

    cudaFuncSetAttribute(fused_kernel,
                         cudaFuncAttributeMaxDynamicSharedMemorySize, SMEM_DYN);

    poison_kernel<<<2048, 256>>>();

    int write_tail = (out_size >= S_LEN * HID + HID) ? 1 : 0;
    fused_kernel<<<NCTA + GEMM_CTAS, TPB, SMEM_DYN>>>(x, Wi, bi, Wh, bh, out, write_tail);
}